// round 2
// baseline (speedup 1.0000x reference)
#include <cuda_runtime.h>
#include <math.h>

#define B_ 2
#define T_ 8192
#define H_ 8
#define D_ 64
#define NC_ 128
#define M_ 4
#define W_ 64
#define BH_ (B_*H_)
#define TT_ (2*T_)
#define OUT_ELEMS ((size_t)B_*H_*T_*D_)

// Scratch (device globals — no allocation at runtime)
__device__ float              g_score[(size_t)BH_*2*NC_*T_];   // 128 MB
__device__ int                g_qidx[BH_*NC_*W_];
__device__ int                g_kidx[BH_*NC_*W_];
__device__ int                g_cnt[BH_*T_];
__device__ double             g_aux;

// ---------------------------------------------------------------------------
// Kernel 0: zero output (atomic target), counts, aux
// ---------------------------------------------------------------------------
__global__ __launch_bounds__(256) void zero_kernel(float* __restrict__ out) {
    size_t i = (size_t)blockIdx.x * 256 + threadIdx.x;
    if (i < OUT_ELEMS) out[i] = 0.f;
    if (i < (size_t)BH_ * T_) g_cnt[i] = 0;
    if (i == 0) g_aux = 0.0;
}

// ---------------------------------------------------------------------------
// Kernel 1: normalize tokens, score vs all centroids, aux-loss accumulation
// score[bh][side][c][tok] = max((x2 + m2_c) - 2*xn.m_c, 0)   == dist^2 (clamped)
// aux term per token      = min_c dist^2
// ---------------------------------------------------------------------------
__global__ __launch_bounds__(256) void dist_kernel(const float* __restrict__ q,
                                                   const float* __restrict__ k,
                                                   const float* __restrict__ means) {
    __shared__ float sm[NC_ * D_];
    __shared__ float sm2[NC_];
    __shared__ float sred[256];
    const int tid = threadIdx.x;
    const int bh  = blockIdx.y;
    const int h   = bh & (H_ - 1);

    const float* mp = means + (size_t)h * NC_ * D_;
    for (int i = tid; i < NC_ * D_; i += 256) sm[i] = mp[i];
    __syncthreads();
    if (tid < NC_) {
        float s = 0.f;
        #pragma unroll
        for (int d = 0; d < D_; d++) { float m = sm[tid * D_ + d]; s += m * m; }
        sm2[tid] = s;
    }
    __syncthreads();

    const int tt   = blockIdx.x * 256 + tid;          // 0 .. 16383
    const int side = (tt >= T_) ? 1 : 0;
    const int tok  = tt - side * T_;
    const float* src = (side ? k : q) + ((size_t)bh * T_ + tok) * D_;

    float x[D_];
    float x2r = 0.f;
    #pragma unroll
    for (int i = 0; i < 16; i++) {
        float4 v = *reinterpret_cast<const float4*>(src + i * 4);
        x[i*4+0] = v.x; x[i*4+1] = v.y; x[i*4+2] = v.z; x[i*4+3] = v.w;
        x2r += v.x*v.x + v.y*v.y + v.z*v.z + v.w*v.w;
    }
    const float s = 1.f / (__fsqrt_rn(x2r) + 1e-6f);
    #pragma unroll
    for (int i = 0; i < D_; i++) x[i] *= s;
    // x2 = sum of normalized elements squared (recompute like the reference does)
    float x2 = 0.f;
    #pragma unroll
    for (int i = 0; i < D_; i++) x2 += x[i] * x[i];

    float* srow = g_score + ((size_t)(bh * 2 + side) * NC_) * T_ + tok;
    float mind2 = 3.402823466e38f;
    for (int c = 0; c < NC_; c++) {
        const float4* mr = reinterpret_cast<const float4*>(sm + c * D_);
        float dot = 0.f;
        #pragma unroll
        for (int i = 0; i < 16; i++) {
            float4 m4 = mr[i];
            dot += x[i*4+0]*m4.x + x[i*4+1]*m4.y + x[i*4+2]*m4.z + x[i*4+3]*m4.w;
        }
        float d2 = fmaxf((x2 + sm2[c]) - 2.f * dot, 0.f);
        srow[(size_t)c * T_] = d2;
        mind2 = fminf(mind2, d2);
    }

    sred[tid] = mind2;
    __syncthreads();
    for (int o = 128; o > 0; o >>= 1) {
        if (tid < o) sred[tid] += sred[tid + o];
        __syncthreads();
    }
    if (tid == 0) atomicAdd(&g_aux, (double)sred[0]);
}

// ---------------------------------------------------------------------------
// Kernel 2: exact top-64 smallest per (bh, side, cluster).
// Histogram on d2 bits (monotone with sqrt ordering); cut-bin refinement uses
// keys = (bits(sqrt_rn(d2)) << 32 | index) to replicate the reference's fp32
// sqrt quantization + lowest-index tie-breaking exactly.
// ---------------------------------------------------------------------------
__global__ __launch_bounds__(256) void select_kernel() {
    extern __shared__ unsigned char sraw[];
    unsigned long long* cand = (unsigned long long*)sraw;             // 8192
    unsigned* hist           = (unsigned*)(sraw + 8192 * 8);          // 2048
    int* selIdx              = (int*)(sraw + 8192 * 8 + 2048 * 4);    // 64

    __shared__ unsigned swsum[8];
    __shared__ unsigned swex[8];
    __shared__ int s_cutbin, s_nbelow, s_nsel, s_ncand;
    __shared__ unsigned long long s_wmin[8], s_min;

    const int tid  = threadIdx.x;
    const int lane = tid & 31, wid = tid >> 5;
    const int c    = blockIdx.x & (NC_ - 1);
    const int side = (blockIdx.x >> 7) & 1;
    const int bh   = blockIdx.x >> 8;
    const float* sc = g_score + ((size_t)((bh * 2 + side) * NC_ + c)) * T_;

    for (int i = tid; i < 2048; i += 256) hist[i] = 0;
    if (tid == 0) { s_nsel = 0; s_ncand = 0; }
    __syncthreads();

    unsigned ord[32];
    #pragma unroll
    for (int j = 0; j < 32; j++) {
        float val = sc[tid + j * 256];        // d2 >= 0 always
        unsigned u = __float_as_uint(val) | 0x80000000u;  // order-preserving (non-neg)
        ord[j] = u;
        atomicAdd(&hist[u >> 21], 1u);
    }
    __syncthreads();

    unsigned bcnt[8]; unsigned ssum = 0;
    #pragma unroll
    for (int j = 0; j < 8; j++) { bcnt[j] = hist[tid * 8 + j]; ssum += bcnt[j]; }
    unsigned v = ssum;
    #pragma unroll
    for (int o = 1; o < 32; o <<= 1) {
        unsigned n = __shfl_up_sync(0xFFFFFFFFu, v, o);
        if (lane >= o) v += n;
    }
    if (lane == 31) swsum[wid] = v;
    __syncthreads();
    if (tid == 0) {
        unsigned run = 0;
        for (int w2 = 0; w2 < 8; w2++) { swex[w2] = run; run += swsum[w2]; }
    }
    __syncthreads();
    unsigned excl = v - ssum + swex[wid];
    if (excl < W_ && excl + ssum >= W_) {
        unsigned cum = excl;
        #pragma unroll
        for (int j = 0; j < 8; j++) {
            if (cum + bcnt[j] >= W_) { s_cutbin = tid * 8 + j; s_nbelow = (int)cum; break; }
            cum += bcnt[j];
        }
    }
    __syncthreads();

    const int cutbin = s_cutbin;
    const int nbelow = s_nbelow;
    #pragma unroll
    for (int j = 0; j < 32; j++) {
        int bin = (int)(ord[j] >> 21);
        if (bin < cutbin) {
            int p = atomicAdd(&s_nsel, 1);
            selIdx[p] = tid + j * 256;
        } else if (bin == cutbin) {
            int p = atomicAdd(&s_ncand, 1);
            // reference comparator: fp32 sqrt of d2, ties -> lowest index
            float d2v = __uint_as_float(ord[j] & 0x7FFFFFFFu);
            unsigned sq = __float_as_uint(__fsqrt_rn(d2v));   // non-negative: bits monotone
            cand[p] = ((unsigned long long)sq << 32) | (unsigned)(tid + j * 256);
        }
    }
    __syncthreads();

    const int r = W_ - nbelow;          // 1..64, candidates >= r
    const int ncand = s_ncand;
    for (int it = 0; it < r; it++) {
        unsigned long long mv = 0xFFFFFFFFFFFFFFFFull;
        for (int p = tid; p < ncand; p += 256) {
            unsigned long long cv = cand[p];
            if (cv < mv) mv = cv;
        }
        #pragma unroll
        for (int o = 16; o; o >>= 1) {
            unsigned long long ov = __shfl_down_sync(0xFFFFFFFFu, mv, o);
            if (ov < mv) mv = ov;
        }
        if (lane == 0) s_wmin[wid] = mv;
        __syncthreads();
        if (tid == 0) {
            unsigned long long m = s_wmin[0];
            for (int w2 = 1; w2 < 8; w2++) if (s_wmin[w2] < m) m = s_wmin[w2];
            s_min = m;
            selIdx[nbelow + it] = (int)(m & 0xFFFFFFFFull);
        }
        __syncthreads();
        unsigned long long m = s_min;
        for (int p = tid; p < ncand; p += 256)
            if (cand[p] == m) cand[p] = 0xFFFFFFFFFFFFFFFFull;
        __syncthreads();
    }

    int* dst = (side == 0 ? g_qidx : g_kidx) + (bh * NC_ + c) * W_;
    if (tid < W_) {
        int idx = selIdx[tid];
        dst[tid] = idx;
        if (side == 0) atomicAdd(&g_cnt[bh * T_ + idx], 1);
    }
}

// ---------------------------------------------------------------------------
// Kernel 3: per-(bh, cluster) attention over [mem(4) ++ kc(64)] and scatter-add.
// ---------------------------------------------------------------------------
#define ATTN_SMEM ((64*65 + 68*65 + 68*65 + 64*68) * 4 + 128 * 4)

__global__ __launch_bounds__(256) void attn_kernel(const float* __restrict__ q,
                                                   const float* __restrict__ k,
                                                   const float* __restrict__ v,
                                                   const float* __restrict__ mk,
                                                   const float* __restrict__ mv,
                                                   float* __restrict__ out) {
    extern __shared__ unsigned char sraw[];
    float* qs   = (float*)sraw;          // 64 x 65
    float* ks   = qs + 64 * 65;          // 68 x 65
    float* vs   = ks + 68 * 65;          // 68 x 65
    float* dots = vs + 68 * 65;          // 64 x 68
    int*   qi   = (int*)(dots + 64 * 68);
    int*   ki   = qi + 64;

    const int tid = threadIdx.x;
    const int c   = blockIdx.x & (NC_ - 1);
    const int bh  = blockIdx.x >> 7;
    const int h   = bh & (H_ - 1);

    if (tid < 64) {
        qi[tid] = g_qidx[(bh * NC_ + c) * W_ + tid];
        ki[tid] = g_kidx[(bh * NC_ + c) * W_ + tid];
    }
    __syncthreads();

    // gather qc
    {
        int row = tid >> 2, cg = tid & 3;
        const float* src = q + ((size_t)bh * T_ + qi[row]) * D_ + cg * 16;
        #pragma unroll
        for (int u = 0; u < 4; u++) {
            float4 t4 = *reinterpret_cast<const float4*>(src + u * 4);
            float* d0 = qs + row * 65 + cg * 16 + u * 4;
            d0[0] = t4.x; d0[1] = t4.y; d0[2] = t4.z; d0[3] = t4.w;
        }
    }
    // gather kf / vf (4 memory rows + 64 gathered rows)
    {
        int cg = tid & 3;
        for (int row = tid >> 2; row < 68; row += 64) {
            const float *sk, *sv;
            if (row < 4) {
                size_t base = ((size_t)(h * NC_ + c) * M_ + row) * D_;
                sk = mk + base; sv = mv + base;
            } else {
                int tk = ki[row - 4];
                sk = k + ((size_t)bh * T_ + tk) * D_;
                sv = v + ((size_t)bh * T_ + tk) * D_;
            }
            #pragma unroll
            for (int u = 0; u < 4; u++) {
                int col = cg * 16 + u * 4;
                float4 a = *reinterpret_cast<const float4*>(sk + col);
                float4 b = *reinterpret_cast<const float4*>(sv + col);
                float* dk = ks + row * 65 + col;
                dk[0] = a.x; dk[1] = a.y; dk[2] = a.z; dk[3] = a.w;
                float* dv = vs + row * 65 + col;
                dv[0] = b.x; dv[1] = b.y; dv[2] = b.z; dv[3] = b.w;
            }
        }
    }
    __syncthreads();

    // QK^T * d^-0.5
    for (int e = tid; e < 64 * 68; e += 256) {
        int i = e / 68, j = e - i * 68;
        const float* qr = qs + i * 65;
        const float* kr = ks + j * 65;
        float acc = 0.f;
        #pragma unroll
        for (int d = 0; d < D_; d++) acc += qr[d] * kr[d];
        dots[e] = acc * 0.125f;
    }
    __syncthreads();

    // softmax rows (one warp handles 8 rows)
    {
        int wid = tid >> 5, lane = tid & 31;
        for (int i = wid * 8; i < wid * 8 + 8; i++) {
            float m = -3.402823466e38f;
            for (int j = lane; j < 68; j += 32) m = fmaxf(m, dots[i * 68 + j]);
            #pragma unroll
            for (int o = 16; o; o >>= 1) m = fmaxf(m, __shfl_xor_sync(0xFFFFFFFFu, m, o));
            float ssum = 0.f;
            for (int j = lane; j < 68; j += 32) {
                float e2 = expf(dots[i * 68 + j] - m);
                dots[i * 68 + j] = e2;
                ssum += e2;
            }
            #pragma unroll
            for (int o = 16; o; o >>= 1) ssum += __shfl_xor_sync(0xFFFFFFFFu, ssum, o);
            float inv = 1.f / ssum;
            for (int j = lane; j < 68; j += 32) dots[i * 68 + j] *= inv;
        }
    }
    __syncthreads();

    // attn @ vf, scatter-add
    for (int e = tid; e < 64 * 64; e += 256) {
        int i = e >> 6, dd = e & 63;
        const float* ar = dots + i * 68;
        float acc = 0.f;
        #pragma unroll
        for (int j = 0; j < 68; j++) acc += ar[j] * vs[j * 65 + dd];
        atomicAdd(&out[((size_t)bh * T_ + qi[i]) * D_ + dd], acc);
    }
}

// ---------------------------------------------------------------------------
// Kernel 4: divide by counts, emit aux loss
// ---------------------------------------------------------------------------
__global__ __launch_bounds__(256) void finalize_kernel(float* __restrict__ out) {
    size_t i = (size_t)blockIdx.x * 256 + threadIdx.x;
    if (i < OUT_ELEMS) {
        float cnt = (float)g_cnt[i >> 6];
        out[i] = out[i] / (cnt + 1e-5f);
    }
    if (i == 0) {
        out[OUT_ELEMS] = (float)(g_aux * (1.0 / ((double)B_ * H_ * 2 * T_ * D_)) * 0.0001);
    }
}

// ---------------------------------------------------------------------------
extern "C" void kernel_launch(void* const* d_in, const int* in_sizes, int n_in,
                              void* d_out, int out_size) {
    const float* q     = (const float*)d_in[0];
    const float* k     = (const float*)d_in[1];
    const float* v     = (const float*)d_in[2];
    const float* means = (const float*)d_in[3];
    const float* mk    = (const float*)d_in[4];
    const float* mv    = (const float*)d_in[5];
    float* out = (float*)d_out;

    cudaFuncSetAttribute(select_kernel, cudaFuncAttributeMaxDynamicSharedMemorySize, 73984);
    cudaFuncSetAttribute(attn_kernel,   cudaFuncAttributeMaxDynamicSharedMemorySize, ATTN_SMEM);

    const int nblk = (int)((OUT_ELEMS + 255) / 256);
    zero_kernel<<<nblk, 256>>>(out);

    dim3 g1(TT_ / 256, BH_);
    dist_kernel<<<g1, 256>>>(q, k, means);

    select_kernel<<<BH_ * 2 * NC_, 256, 73984>>>();

    attn_kernel<<<BH_ * NC_, 256, ATTN_SMEM>>>(q, k, v, mk, mv, out);

    finalize_kernel<<<nblk, 256>>>(out);
}

// round 5
// speedup vs baseline: 2.9751x; 2.9751x over previous
#include <cuda_runtime.h>
#include <math.h>

#define B_ 2
#define T_ 8192
#define H_ 8
#define D_ 64
#define NC_ 128
#define M_ 4
#define W_ 64
#define BH_ (B_*H_)
#define TT_ (2*T_)
#define OUT_ELEMS ((size_t)B_*H_*T_*D_)

__device__ float              g_score[(size_t)BH_*2*NC_*T_];   // 128 MB
__device__ int                g_qidx[BH_*NC_*W_];
__device__ int                g_kidx[BH_*NC_*W_];
__device__ int                g_cnt[BH_*T_];
__device__ double             g_aux;

// ---- f32x2 helpers (sm_100+) ----
__device__ __forceinline__ unsigned long long pack2(float lo, float hi) {
    unsigned long long r;
    asm("mov.b64 %0, {%1,%2};" : "=l"(r) : "f"(lo), "f"(hi));
    return r;
}
__device__ __forceinline__ unsigned long long fma2(unsigned long long a, unsigned long long b, unsigned long long c) {
    unsigned long long d;
    asm("fma.rn.f32x2 %0, %1, %2, %3;" : "=l"(d) : "l"(a), "l"(b), "l"(c));
    return d;
}
__device__ __forceinline__ void unpack2(unsigned long long v, float& lo, float& hi) {
    asm("mov.b64 {%0,%1}, %2;" : "=f"(lo), "=f"(hi) : "l"(v));
}

// ---------------------------------------------------------------------------
// Kernel 0: zero output (atomic target), counts, aux
// ---------------------------------------------------------------------------
__global__ __launch_bounds__(256) void zero_kernel(float* __restrict__ out) {
    size_t i = (size_t)blockIdx.x * 256 + threadIdx.x;
    if (i < OUT_ELEMS / 4) reinterpret_cast<float4*>(out)[i] = make_float4(0.f, 0.f, 0.f, 0.f);
    if (i < (size_t)BH_ * T_) g_cnt[i] = 0;
    if (i == 0) g_aux = 0.0;
}

// ---------------------------------------------------------------------------
// Kernel 1 (EXACT R2 source — proven-passing d2 values): normalize tokens,
// score vs all centroids, aux-loss accumulation.
// ---------------------------------------------------------------------------
__global__ __launch_bounds__(256) void dist_kernel(const float* __restrict__ q,
                                                   const float* __restrict__ k,
                                                   const float* __restrict__ means) {
    __shared__ float sm[NC_ * D_];
    __shared__ float sm2[NC_];
    __shared__ float sred[256];
    const int tid = threadIdx.x;
    const int bh  = blockIdx.y;
    const int h   = bh & (H_ - 1);

    const float* mp = means + (size_t)h * NC_ * D_;
    for (int i = tid; i < NC_ * D_; i += 256) sm[i] = mp[i];
    __syncthreads();
    if (tid < NC_) {
        float s = 0.f;
        #pragma unroll
        for (int d = 0; d < D_; d++) { float m = sm[tid * D_ + d]; s += m * m; }
        sm2[tid] = s;
    }
    __syncthreads();

    const int tt   = blockIdx.x * 256 + tid;          // 0 .. 16383
    const int side = (tt >= T_) ? 1 : 0;
    const int tok  = tt - side * T_;
    const float* src = (side ? k : q) + ((size_t)bh * T_ + tok) * D_;

    float x[D_];
    float x2r = 0.f;
    #pragma unroll
    for (int i = 0; i < 16; i++) {
        float4 v = *reinterpret_cast<const float4*>(src + i * 4);
        x[i*4+0] = v.x; x[i*4+1] = v.y; x[i*4+2] = v.z; x[i*4+3] = v.w;
        x2r += v.x*v.x + v.y*v.y + v.z*v.z + v.w*v.w;
    }
    const float s = 1.f / (__fsqrt_rn(x2r) + 1e-6f);
    #pragma unroll
    for (int i = 0; i < D_; i++) x[i] *= s;
    float x2 = 0.f;
    #pragma unroll
    for (int i = 0; i < D_; i++) x2 += x[i] * x[i];

    float* srow = g_score + ((size_t)(bh * 2 + side) * NC_) * T_ + tok;
    float mind2 = 3.402823466e38f;
    for (int c = 0; c < NC_; c++) {
        const float4* mr = reinterpret_cast<const float4*>(sm + c * D_);
        float dot = 0.f;
        #pragma unroll
        for (int i = 0; i < 16; i++) {
            float4 m4 = mr[i];
            dot += x[i*4+0]*m4.x + x[i*4+1]*m4.y + x[i*4+2]*m4.z + x[i*4+3]*m4.w;
        }
        float d2 = fmaxf((x2 + sm2[c]) - 2.f * dot, 0.f);
        srow[(size_t)c * T_] = d2;
        mind2 = fminf(mind2, d2);
    }

    sred[tid] = mind2;
    __syncthreads();
    for (int o = 128; o > 0; o >>= 1) {
        if (tid < o) sred[tid] += sred[tid + o];
        __syncthreads();
    }
    if (tid == 0) atomicAdd(&g_aux, (double)sred[0]);
}

// ---------------------------------------------------------------------------
// Kernel 2: exact top-64 smallest per (bh, side, cluster).
// Two-level histogram; candidates = sub-bins [cut2-1, cut2+1] (two-sided!)
// so every fp32-sqrt tie group (span <= 2 d2-ulps) containing the rank-64
// element is fully inside the candidate set; refinement keys
// (bits(sqrt_rn(d2))<<32 | idx) replicate the reference comparator exactly.
// ---------------------------------------------------------------------------
__global__ __launch_bounds__(256) void select_kernel() {
    __shared__ unsigned long long cand[2048];
    __shared__ unsigned hist[2048];
    __shared__ int selIdx[64];
    __shared__ unsigned swsum[8];
    __shared__ unsigned swex[8];
    __shared__ int s_cut, s_nbelow, s_nsel, s_ncand;
    __shared__ unsigned long long s_wmin[8], s_min;

    const int tid  = threadIdx.x;
    const int lane = tid & 31, wid = tid >> 5;
    const int c    = blockIdx.x & (NC_ - 1);
    const int side = (blockIdx.x >> 7) & 1;
    const int bh   = blockIdx.x >> 8;
    const float* sc = g_score + ((size_t)((bh * 2 + side) * NC_ + c)) * T_;

    for (int i = tid; i < 2048; i += 256) hist[i] = 0;
    if (tid == 0) { s_nsel = 0; s_ncand = 0; }
    __syncthreads();

    unsigned ord[32];
    #pragma unroll
    for (int j = 0; j < 32; j++) {
        unsigned u = __float_as_uint(sc[tid + j * 256]) | 0x80000000u;  // d2>=0: monotone
        ord[j] = u;
        atomicAdd(&hist[u >> 21], 1u);
    }
    __syncthreads();

    // ---- scan pass 1 (threshold W_) ----
    {
        unsigned bcnt[8]; unsigned ssum = 0;
        #pragma unroll
        for (int j = 0; j < 8; j++) { bcnt[j] = hist[tid * 8 + j]; ssum += bcnt[j]; }
        unsigned v = ssum;
        #pragma unroll
        for (int o = 1; o < 32; o <<= 1) {
            unsigned n = __shfl_up_sync(0xFFFFFFFFu, v, o);
            if (lane >= o) v += n;
        }
        if (lane == 31) swsum[wid] = v;
        __syncthreads();
        if (tid == 0) { unsigned run = 0; for (int w2 = 0; w2 < 8; w2++) { swex[w2] = run; run += swsum[w2]; } }
        __syncthreads();
        unsigned excl = v - ssum + swex[wid];
        if (excl < W_ && excl + ssum >= W_) {
            unsigned cum = excl;
            #pragma unroll
            for (int j = 0; j < 8; j++) {
                if (cum + bcnt[j] >= W_) { s_cut = tid * 8 + j; s_nbelow = (int)cum; break; }
                cum += bcnt[j];
            }
        }
    }
    __syncthreads();
    const int cut1 = s_cut;
    const int nbelow1 = s_nbelow;
    const int r1 = W_ - nbelow1;
    __syncthreads();

    // ---- pass 2: re-histogram cut1 members on bits [20:10] ----
    for (int i = tid; i < 2048; i += 256) hist[i] = 0;
    __syncthreads();
    #pragma unroll
    for (int j = 0; j < 32; j++)
        if ((int)(ord[j] >> 21) == cut1) atomicAdd(&hist[(ord[j] >> 10) & 0x7FFu], 1u);
    __syncthreads();

    {
        unsigned bcnt[8]; unsigned ssum = 0;
        #pragma unroll
        for (int j = 0; j < 8; j++) { bcnt[j] = hist[tid * 8 + j]; ssum += bcnt[j]; }
        unsigned v = ssum;
        #pragma unroll
        for (int o = 1; o < 32; o <<= 1) {
            unsigned n = __shfl_up_sync(0xFFFFFFFFu, v, o);
            if (lane >= o) v += n;
        }
        if (lane == 31) swsum[wid] = v;
        __syncthreads();
        if (tid == 0) { unsigned run = 0; for (int w2 = 0; w2 < 8; w2++) { swex[w2] = run; run += swsum[w2]; } }
        __syncthreads();
        unsigned excl = v - ssum + swex[wid];
        if ((int)excl < r1 && (int)(excl + ssum) >= r1) {
            unsigned cum = excl;
            #pragma unroll
            for (int j = 0; j < 8; j++) {
                if ((int)(cum + bcnt[j]) >= r1) { s_cut = tid * 8 + j; s_nbelow = (int)cum; break; }
                cum += bcnt[j];
            }
        }
    }
    __syncthreads();
    const int cut2 = s_cut;
    // two-sided widening: candidates in sub-bins [cutlo, cuthi]
    const int cutlo = (cut2 > 0) ? (cut2 - 1) : 0;
    const int cuthi = (cut2 < 2047) ? (cut2 + 1) : 2047;
    const int nbelow2 = s_nbelow - ((cut2 > 0) ? (int)hist[cut2 - 1] : 0);

    // ---- classify ----
    #pragma unroll
    for (int j = 0; j < 32; j++) {
        int b1 = (int)(ord[j] >> 21);
        if (b1 > cut1) continue;
        if (b1 < cut1) {
            selIdx[atomicAdd(&s_nsel, 1)] = tid + j * 256;
        } else {
            int b2 = (int)((ord[j] >> 10) & 0x7FFu);
            if (b2 < cutlo) {
                selIdx[atomicAdd(&s_nsel, 1)] = tid + j * 256;
            } else if (b2 <= cuthi) {
                int p = atomicAdd(&s_ncand, 1);
                if (p < 2048) {
                    float d2v = __uint_as_float(ord[j] & 0x7FFFFFFFu);
                    unsigned sq = __float_as_uint(__fsqrt_rn(d2v));
                    cand[p] = ((unsigned long long)sq << 32) | (unsigned)(tid + j * 256);
                }
            }
        }
    }
    __syncthreads();

    const int nbelow = nbelow1 + nbelow2;
    const int r = W_ - nbelow;
    const int ncand = min(s_ncand, 2048);
    for (int it = 0; it < r; it++) {
        unsigned long long mv = 0xFFFFFFFFFFFFFFFFull;
        for (int p = tid; p < ncand; p += 256) {
            unsigned long long cv = cand[p];
            if (cv < mv) mv = cv;
        }
        #pragma unroll
        for (int o = 16; o; o >>= 1) {
            unsigned long long ov = __shfl_down_sync(0xFFFFFFFFu, mv, o);
            if (ov < mv) mv = ov;
        }
        if (lane == 0) s_wmin[wid] = mv;
        __syncthreads();
        if (tid == 0) {
            unsigned long long m = s_wmin[0];
            for (int w2 = 1; w2 < 8; w2++) if (s_wmin[w2] < m) m = s_wmin[w2];
            s_min = m;
            selIdx[nbelow + it] = (int)(m & 0xFFFFFFFFull);
        }
        __syncthreads();
        unsigned long long m = s_min;
        for (int p = tid; p < ncand; p += 256)
            if (cand[p] == m) cand[p] = 0xFFFFFFFFFFFFFFFFull;
        __syncthreads();
    }

    int* dst = (side == 0 ? g_qidx : g_kidx) + (bh * NC_ + c) * W_;
    if (tid < W_) {
        int idx = selIdx[tid];
        dst[tid] = idx;
        if (side == 0) atomicAdd(&g_cnt[bh * T_ + idx], 1);
    }
}

// ---------------------------------------------------------------------------
// Kernel 3: per-(bh, cluster) attention. 4x4 register tiles + f32x2 FMA.
// ---------------------------------------------------------------------------
#define QS_OFF   0
#define KS_OFF   (64*68)
#define VS_OFF   (KS_OFF + 64*68)
#define DT_OFF   (VS_OFF + 68*64)
#define FLOATS_T (DT_OFF + 68*68)
#define ATTN_SMEM (FLOATS_T*4 + 2*64*4)

__global__ __launch_bounds__(256) void attn_kernel(const float* __restrict__ q,
                                                   const float* __restrict__ k,
                                                   const float* __restrict__ v,
                                                   const float* __restrict__ mk,
                                                   const float* __restrict__ mv,
                                                   float* __restrict__ out) {
    extern __shared__ float sf[];
    float* qs_t = sf + QS_OFF;
    float* ks_t = sf + KS_OFF;
    float* vs   = sf + VS_OFF;
    float* dt   = sf + DT_OFF;
    int*   qi   = (int*)(sf + FLOATS_T);
    int*   ki   = qi + 64;

    const int tid = threadIdx.x;
    const int c   = blockIdx.x & (NC_ - 1);
    const int bh  = blockIdx.x >> 7;
    const int h   = bh & (H_ - 1);

    if (tid < 64) {
        qi[tid] = g_qidx[(bh * NC_ + c) * W_ + tid];
        ki[tid] = g_kidx[(bh * NC_ + c) * W_ + tid];
    }
    __syncthreads();

    // gather q -> qs_t (transposed)
    {
        int row = tid >> 2, cg = tid & 3;
        const float* src = q + ((size_t)bh * T_ + qi[row]) * D_ + cg * 16;
        #pragma unroll
        for (int u = 0; u < 4; u++) {
            float4 t4 = *reinterpret_cast<const float4*>(src + u * 4);
            int d0 = cg * 16 + u * 4;
            qs_t[(d0+0)*68 + row] = t4.x;
            qs_t[(d0+1)*68 + row] = t4.y;
            qs_t[(d0+2)*68 + row] = t4.z;
            qs_t[(d0+3)*68 + row] = t4.w;
        }
    }
    // gather kf -> ks_t (transposed), vf -> vs (natural). rows 0..3 = memory.
    {
        int cg = tid & 3;
        for (int row = tid >> 2; row < 68; row += 64) {
            const float *sk, *sv;
            if (row < 4) {
                size_t base = ((size_t)(h * NC_ + c) * M_ + row) * D_;
                sk = mk + base; sv = mv + base;
            } else {
                int tk = ki[row - 4];
                sk = k + ((size_t)bh * T_ + tk) * D_;
                sv = v + ((size_t)bh * T_ + tk) * D_;
            }
            #pragma unroll
            for (int u = 0; u < 4; u++) {
                int d0 = cg * 16 + u * 4;
                float4 a = *reinterpret_cast<const float4*>(sk + d0);
                float4 b = *reinterpret_cast<const float4*>(sv + d0);
                ks_t[(d0+0)*68 + row] = a.x;
                ks_t[(d0+1)*68 + row] = a.y;
                ks_t[(d0+2)*68 + row] = a.z;
                ks_t[(d0+3)*68 + row] = a.w;
                *reinterpret_cast<float4*>(&vs[row * 64 + d0]) = b;
            }
        }
    }
    __syncthreads();

    const int tx = tid & 15, ty = tid >> 4;
    const int r0 = 4 * ty, c0 = 4 * tx;

    // QK^T main tile
    {
        unsigned long long a00=0, a01=0, a10=0, a11=0, a20=0, a21=0, a30=0, a31=0;
        #pragma unroll 8
        for (int d = 0; d < D_; d++) {
            float4 q4 = *reinterpret_cast<const float4*>(&qs_t[d * 68 + r0]);
            ulonglong2 k2 = *reinterpret_cast<const ulonglong2*>(&ks_t[d * 68 + c0]);
            unsigned long long p0 = pack2(q4.x, q4.x);
            unsigned long long p1 = pack2(q4.y, q4.y);
            unsigned long long p2 = pack2(q4.z, q4.z);
            unsigned long long p3 = pack2(q4.w, q4.w);
            a00 = fma2(p0, k2.x, a00); a01 = fma2(p0, k2.y, a01);
            a10 = fma2(p1, k2.x, a10); a11 = fma2(p1, k2.y, a11);
            a20 = fma2(p2, k2.x, a20); a21 = fma2(p2, k2.y, a21);
            a30 = fma2(p3, k2.x, a30); a31 = fma2(p3, k2.y, a31);
        }
        unsigned long long accs[4][2] = {{a00,a01},{a10,a11},{a20,a21},{a30,a31}};
        #pragma unroll
        for (int r = 0; r < 4; r++) {
            float v0, v1, v2, v3;
            unpack2(accs[r][0], v0, v1);
            unpack2(accs[r][1], v2, v3);
            dt[(c0+0)*68 + r0 + r] = v0 * 0.125f;
            dt[(c0+1)*68 + r0 + r] = v1 * 0.125f;
            dt[(c0+2)*68 + r0 + r] = v2 * 0.125f;
            dt[(c0+3)*68 + r0 + r] = v3 * 0.125f;
        }
    }
    // QK^T extra cols 64..67
    {
        int i = tid >> 2, jm = 64 + (tid & 3);
        float acc = 0.f;
        #pragma unroll 8
        for (int d = 0; d < D_; d++) acc += qs_t[d * 68 + i] * ks_t[d * 68 + jm];
        dt[jm * 68 + i] = acc * 0.125f;
    }
    __syncthreads();

    // softmax over j (0..67) per row i
    {
        int w2 = tid >> 5, lane = tid & 31;
        for (int i = w2 * 8; i < w2 * 8 + 8; i++) {
            float m = -3.402823466e38f;
            for (int j = lane; j < 68; j += 32) m = fmaxf(m, dt[j * 68 + i]);
            #pragma unroll
            for (int o = 16; o; o >>= 1) m = fmaxf(m, __shfl_xor_sync(0xFFFFFFFFu, m, o));
            float ssum = 0.f;
            for (int j = lane; j < 68; j += 32) {
                float e2 = expf(dt[j * 68 + i] - m);
                dt[j * 68 + i] = e2;
                ssum += e2;
            }
            #pragma unroll
            for (int o = 16; o; o >>= 1) ssum += __shfl_xor_sync(0xFFFFFFFFu, ssum, o);
            float inv = 1.f / ssum;
            for (int j = lane; j < 68; j += 32) dt[j * 68 + i] *= inv;
        }
    }
    __syncthreads();

    // attn @ vf, scatter float4 atomics
    {
        unsigned long long a00=0, a01=0, a10=0, a11=0, a20=0, a21=0, a30=0, a31=0;
        #pragma unroll 4
        for (int j = 0; j < 68; j++) {
            float4 a4 = *reinterpret_cast<const float4*>(&dt[j * 68 + r0]);
            ulonglong2 v2 = *reinterpret_cast<const ulonglong2*>(&vs[j * 64 + c0]);
            unsigned long long p0 = pack2(a4.x, a4.x);
            unsigned long long p1 = pack2(a4.y, a4.y);
            unsigned long long p2 = pack2(a4.z, a4.z);
            unsigned long long p3 = pack2(a4.w, a4.w);
            a00 = fma2(p0, v2.x, a00); a01 = fma2(p0, v2.y, a01);
            a10 = fma2(p1, v2.x, a10); a11 = fma2(p1, v2.y, a11);
            a20 = fma2(p2, v2.x, a20); a21 = fma2(p2, v2.y, a21);
            a30 = fma2(p3, v2.x, a30); a31 = fma2(p3, v2.y, a31);
        }
        unsigned long long accs[4][2] = {{a00,a01},{a10,a11},{a20,a21},{a30,a31}};
        #pragma unroll
        for (int r = 0; r < 4; r++) {
            float4 o4;
            unpack2(accs[r][0], o4.x, o4.y);
            unpack2(accs[r][1], o4.z, o4.w);
            float* dst = &out[((size_t)bh * T_ + qi[r0 + r]) * D_ + c0];
            atomicAdd(reinterpret_cast<float4*>(dst), o4);
        }
    }
}

// ---------------------------------------------------------------------------
// Kernel 4: divide by counts, emit aux loss
// ---------------------------------------------------------------------------
__global__ __launch_bounds__(256) void finalize_kernel(float* __restrict__ out) {
    size_t i = (size_t)blockIdx.x * 256 + threadIdx.x;
    if (i < OUT_ELEMS / 4) {
        float cnt = (float)g_cnt[i >> 4];
        float inv = 1.f / (cnt + 1e-5f);
        float4 o = reinterpret_cast<float4*>(out)[i];
        o.x *= inv; o.y *= inv; o.z *= inv; o.w *= inv;
        reinterpret_cast<float4*>(out)[i] = o;
    }
    if (i == 0) {
        out[OUT_ELEMS] = (float)(g_aux * (1.0 / ((double)B_ * H_ * 2 * T_ * D_)) * 0.0001);
    }
}

// ---------------------------------------------------------------------------
extern "C" void kernel_launch(void* const* d_in, const int* in_sizes, int n_in,
                              void* d_out, int out_size) {
    const float* q     = (const float*)d_in[0];
    const float* k     = (const float*)d_in[1];
    const float* v     = (const float*)d_in[2];
    const float* means = (const float*)d_in[3];
    const float* mk    = (const float*)d_in[4];
    const float* mv    = (const float*)d_in[5];
    float* out = (float*)d_out;

    cudaFuncSetAttribute(attn_kernel, cudaFuncAttributeMaxDynamicSharedMemorySize, ATTN_SMEM);

    const int nblk4 = (int)((OUT_ELEMS / 4 + 255) / 256);
    zero_kernel<<<nblk4, 256>>>(out);

    dim3 g1(TT_ / 256, BH_);
    dist_kernel<<<g1, 256>>>(q, k, means);

    select_kernel<<<BH_ * 2 * NC_, 256>>>();

    attn_kernel<<<BH_ * NC_, 256, ATTN_SMEM>>>(q, k, v, mk, mv, out);

    finalize_kernel<<<nblk4, 256>>>(out);
}